// round 2
// baseline (speedup 1.0000x reference)
#include <cuda_runtime.h>
#include <math.h>

#define Hdim 2048
#define Idim 4096
#define Edim 8
#define Tdim 2048
#define TK   4096   // T * K, always exact since every token picks exactly 2 experts

// ---------------- scratch (static device arrays; no allocations) ----------------
__device__ float d_tn[(size_t)Tdim * Hdim];   // normalized tokens, 16 MB
__device__ float d_g[(size_t)TK * Idim];      // gate proj, 64 MB
__device__ float d_u[(size_t)TK * Idim];      // up proj, 64 MB
__device__ float d_h[(size_t)TK * Idim];      // silu(g)*u, 64 MB
__device__ int   d_rows[TK];                  // token id per expert-row slot
__device__ float d_wgt[TK];                   // combine weight per slot
__device__ int   d_topi[Tdim * 2];
__device__ float d_topw[Tdim * 2];
__device__ int   d_counts[Edim];
__device__ int   d_cursor[Edim];
__device__ int   d_offsets[Edim + 1];

// ---------------- helpers ----------------
__device__ __forceinline__ float warpsum(float v) {
#pragma unroll
    for (int o = 16; o > 0; o >>= 1) v += __shfl_down_sync(0xFFFFFFFFu, v, o);
    return v;
}

__device__ __forceinline__ unsigned f2tf(float x) {
    unsigned u;
    asm("cvt.rna.tf32.f32 %0, %1;" : "=r"(u) : "f"(x));
    return u;
}

__device__ __forceinline__ void mma_tf32(float c[4],
                                         unsigned a0, unsigned a1, unsigned a2, unsigned a3,
                                         unsigned b0, unsigned b1) {
    asm volatile(
        "mma.sync.aligned.m16n8k8.row.col.f32.tf32.tf32.f32 "
        "{%0,%1,%2,%3}, {%4,%5,%6,%7}, {%8,%9}, {%0,%1,%2,%3};"
        : "+f"(c[0]), "+f"(c[1]), "+f"(c[2]), "+f"(c[3])
        : "r"(a0), "r"(a1), "r"(a2), "r"(a3), "r"(b0), "r"(b1));
}

// ---------------- init: zero output + counters ----------------
__global__ void init_kernel(float* __restrict__ out) {
    size_t n = (size_t)Tdim * Hdim;
    for (size_t i = (size_t)blockIdx.x * blockDim.x + threadIdx.x; i < n;
         i += (size_t)gridDim.x * blockDim.x)
        out[i] = 0.0f;
    if (blockIdx.x == 0 && threadIdx.x < Edim) {
        d_counts[threadIdx.x] = 0;
        d_cursor[threadIdx.x] = 0;
    }
}

// ---------------- RMSNorm + router logits + softmax + top-2 ----------------
__global__ __launch_bounds__(256) void routing_kernel(const float* __restrict__ x,
                                                      const float* __restrict__ nw,
                                                      const float* __restrict__ rw) {
    int t = blockIdx.x, tid = threadIdx.x, lane = tid & 31, warp = tid >> 5;
    const float* xr = x + (size_t)t * Hdim;
    __shared__ float sred[8];
    __shared__ float slog[8][9];
    __shared__ float s_rms;

    float ss = 0.0f;
    for (int i = tid; i < Hdim; i += 256) { float v = xr[i]; ss += v * v; }
    ss = warpsum(ss);
    if (lane == 0) sred[warp] = ss;
    __syncthreads();
    if (tid == 0) {
        float tot = 0.0f;
        for (int w = 0; w < 8; w++) tot += sred[w];
        s_rms = rsqrtf(tot / (float)Hdim + 1e-6f);
    }
    __syncthreads();
    float rms = s_rms;

    float acc[8];
#pragma unroll
    for (int e = 0; e < 8; e++) acc[e] = 0.0f;
    for (int i = tid; i < Hdim; i += 256) {
        float tv = xr[i] * rms * nw[i];
        d_tn[(size_t)t * Hdim + i] = tv;
#pragma unroll
        for (int e = 0; e < 8; e++) acc[e] += tv * rw[i * Edim + e];
    }
#pragma unroll
    for (int e = 0; e < 8; e++) {
        float v = warpsum(acc[e]);
        if (lane == 0) slog[warp][e] = v;
    }
    __syncthreads();
    if (tid == 0) {
        float lg[8];
        for (int e = 0; e < 8; e++) {
            float s = 0.0f;
            for (int w = 0; w < 8; w++) s += slog[w][e];
            lg[e] = s;
        }
        float mx = lg[0];
        for (int e = 1; e < 8; e++) mx = fmaxf(mx, lg[e]);
        float af[8], sum = 0.0f;
        for (int e = 0; e < 8; e++) { af[e] = expf(lg[e] - mx); sum += af[e]; }
        float inv = 1.0f / sum;
        for (int e = 0; e < 8; e++) af[e] *= inv;
        int i1 = 0;
        for (int e = 1; e < 8; e++) if (af[e] > af[i1]) i1 = e;
        int i2 = (i1 == 0) ? 1 : 0;
        for (int e = 0; e < 8; e++) if (e != i1 && af[e] > af[i2]) i2 = e;
        float v1 = af[i1], v2 = af[i2], s2 = v1 + v2;
        d_topi[2 * t] = i1;  d_topi[2 * t + 1] = i2;
        d_topw[2 * t] = v1 / s2;  d_topw[2 * t + 1] = v2 / s2;
        atomicAdd(&d_counts[i1], 1);
        atomicAdd(&d_counts[i2], 1);
    }
}

__global__ void scan_kernel() {
    if (threadIdx.x == 0) {
        int o = 0;
        for (int e = 0; e < Edim; e++) { d_offsets[e] = o; o += d_counts[e]; }
        d_offsets[Edim] = o;
    }
}

__global__ void assign_kernel() {
    int t = blockIdx.x * blockDim.x + threadIdx.x;
    if (t >= Tdim) return;
    for (int k = 0; k < 2; k++) {
        int e = d_topi[2 * t + k];
        int p = d_offsets[e] + atomicAdd(&d_cursor[e], 1);
        d_rows[p] = t;
        d_wgt[p] = d_topw[2 * t + k];
    }
}

// ---------------- grouped GEMM (tf32 mma.sync), 256x32x16 block tile ----------------
// MODE 0: gate  (A = gathered d_tn, C = d_g)        N=Idim, K=Hdim
// MODE 1: up    (A = gathered d_tn, C = d_u)        N=Idim, K=Hdim
// MODE 2: down  (A = d_h rows,     atomic C = out)  N=Hdim, K=Idim
#define BM 256
#define BN 32
#define BK 16

template <int MODE>
__global__ __launch_bounds__(256) void gemm_kernel(const float* __restrict__ Ball,
                                                   float* __restrict__ Out) {
    constexpr int NDIM = (MODE == 2) ? Hdim : Idim;
    constexpr int KDIM = (MODE == 2) ? Idim : Hdim;

    int e = blockIdx.z;
    int cnt = d_counts[e];
    int m0 = blockIdx.y * BM;
    if (m0 >= cnt) return;
    int base = d_offsets[e];
    int n0 = blockIdx.x * BN;
    const float* Bmat = Ball + (size_t)e * KDIM * NDIM;

    __shared__ float As[BK][BM + 4];   // [k][m], stride 260 (== 4 mod 32)
    __shared__ float Bs[BK][BN + 4];   // [k][n], stride 36

    int tid = threadIdx.x, lane = tid & 31, warp = tid >> 5;
    int valid = cnt - m0;

    const float* Arow = nullptr;
    if (tid < valid) {
        if (MODE < 2) {
            int tok = d_rows[base + m0 + tid];
            Arow = d_tn + (size_t)tok * KDIM;
        } else {
            Arow = d_h + (size_t)(base + m0 + tid) * KDIM;
        }
    }

    float acc[2][4][4];
#pragma unroll
    for (int mf = 0; mf < 2; mf++)
#pragma unroll
        for (int nf = 0; nf < 4; nf++)
#pragma unroll
            for (int q = 0; q < 4; q++) acc[mf][nf][q] = 0.0f;

    int mw = warp * 32;

    for (int k0 = 0; k0 < KDIM; k0 += BK) {
        // load A tile (each thread owns one m-row)
        if (Arow) {
#pragma unroll
            for (int j = 0; j < 4; j++) {
                float4 v = *(const float4*)(Arow + k0 + j * 4);
                As[j * 4 + 0][tid] = v.x;
                As[j * 4 + 1][tid] = v.y;
                As[j * 4 + 2][tid] = v.z;
                As[j * 4 + 3][tid] = v.w;
            }
        } else {
#pragma unroll
            for (int j = 0; j < BK; j++) As[j][tid] = 0.0f;
        }
        // load B tile (16x32 floats, 128 threads x float4)
        if (tid < 128) {
            int kk = tid >> 3, nn = (tid & 7) * 4;
            float4 v = *(const float4*)(Bmat + (size_t)(k0 + kk) * NDIM + n0 + nn);
            Bs[kk][nn + 0] = v.x;
            Bs[kk][nn + 1] = v.y;
            Bs[kk][nn + 2] = v.z;
            Bs[kk][nn + 3] = v.w;
        }
        __syncthreads();

#pragma unroll
        for (int ks = 0; ks < BK; ks += 8) {
            unsigned a[2][4], b[4][2];
#pragma unroll
            for (int mf = 0; mf < 2; mf++) {
                int r = mw + mf * 16 + (lane >> 2);
                a[mf][0] = f2tf(As[ks + (lane & 3)][r]);
                a[mf][1] = f2tf(As[ks + (lane & 3)][r + 8]);
                a[mf][2] = f2tf(As[ks + 4 + (lane & 3)][r]);
                a[mf][3] = f2tf(As[ks + 4 + (lane & 3)][r + 8]);
            }
#pragma unroll
            for (int nf = 0; nf < 4; nf++) {
                int c = nf * 8 + (lane >> 2);
                b[nf][0] = f2tf(Bs[ks + (lane & 3)][c]);
                b[nf][1] = f2tf(Bs[ks + 4 + (lane & 3)][c]);
            }
#pragma unroll
            for (int mf = 0; mf < 2; mf++)
#pragma unroll
                for (int nf = 0; nf < 4; nf++)
                    mma_tf32(acc[mf][nf], a[mf][0], a[mf][1], a[mf][2], a[mf][3],
                             b[nf][0], b[nf][1]);
        }
        __syncthreads();
    }

    // epilogue
#pragma unroll
    for (int mf = 0; mf < 2; mf++) {
        int rbase = mw + mf * 16 + (lane >> 2);
#pragma unroll
        for (int nf = 0; nf < 4; nf++) {
            int c = n0 + nf * 8 + (lane & 3) * 2;
#pragma unroll
            for (int half = 0; half < 2; half++) {
                int r = rbase + half * 8;
                float v0 = acc[mf][nf][half * 2 + 0];
                float v1 = acc[mf][nf][half * 2 + 1];
                if (r < valid) {
                    if (MODE == 2) {
                        int gp = base + m0 + r;
                        int tok = d_rows[gp];
                        float w = d_wgt[gp];
                        atomicAdd(&Out[(size_t)tok * NDIM + c + 0], w * v0);
                        atomicAdd(&Out[(size_t)tok * NDIM + c + 1], w * v1);
                    } else {
                        float* C = (MODE == 0) ? d_g : d_u;
                        size_t o = (size_t)(base + m0 + r) * NDIM + c;
                        C[o + 0] = v0;
                        C[o + 1] = v1;
                    }
                }
            }
        }
    }
}

// ---------------- h = silu(g) * u ----------------
__global__ void silu_kernel() {
    size_t n = (size_t)TK * Idim;
    for (size_t i = (size_t)blockIdx.x * blockDim.x + threadIdx.x; i < n;
         i += (size_t)gridDim.x * blockDim.x) {
        float g = d_g[i], u = d_u[i];
        d_h[i] = g / (1.0f + expf(-g)) * u;
    }
}

// ---------------- launch ----------------
extern "C" void kernel_launch(void* const* d_in, const int* in_sizes, int n_in,
                              void* d_out, int out_size) {
    const float* x  = (const float*)d_in[0];
    const float* nw = (const float*)d_in[1];
    const float* rw = (const float*)d_in[2];
    const float* wg = (const float*)d_in[3];
    const float* wu = (const float*)d_in[4];
    const float* wd = (const float*)d_in[5];
    float* out = (float*)d_out;

    init_kernel<<<512, 256>>>(out);
    routing_kernel<<<Tdim, 256>>>(x, nw, rw);
    scan_kernel<<<1, 32>>>();
    assign_kernel<<<Tdim / 256, 256>>>();

    dim3 g1(Idim / BN, Tdim / BM, Edim);   // 128 x 8 x 8
    gemm_kernel<0><<<g1, 256>>>(wg, nullptr);
    gemm_kernel<1><<<g1, 256>>>(wu, nullptr);
    silu_kernel<<<2048, 256>>>();

    dim3 g2(Hdim / BN, Tdim / BM, Edim);   // 64 x 8 x 8
    gemm_kernel<2><<<g2, 256>>>(wd, out);
}

// round 4
// speedup vs baseline: 4.3672x; 4.3672x over previous
#include <cuda_runtime.h>
#include <math.h>
#include <stdint.h>

#define Hdim 2048
#define Idim 4096
#define Edim 8
#define Tdim 2048
#define TK   4096   // T * K slots (always exact: every token picks 2 experts)

// ---------------- scratch (static device arrays; no allocations) ----------------
__device__ float d_tn[(size_t)Tdim * Hdim];   // normalized tokens (tf32-rounded)
__device__ float d_h[(size_t)TK * Idim];      // silu(g)*u (tf32-rounded)
__device__ int   d_rows[TK];
__device__ float d_wgt[TK];
__device__ int   d_topi[Tdim * 2];
__device__ float d_topw[Tdim * 2];
__device__ int   d_counts[Edim];
__device__ int   d_cursor[Edim];
__device__ int   d_offsets[Edim + 1];

// ---------------- helpers ----------------
__device__ __forceinline__ float warpsum(float v) {
#pragma unroll
    for (int o = 16; o > 0; o >>= 1) v += __shfl_down_sync(0xFFFFFFFFu, v, o);
    return v;
}
__device__ __forceinline__ unsigned f2tf(float x) {
    unsigned u;
    asm("cvt.rna.tf32.f32 %0, %1;" : "=r"(u) : "f"(x));
    return u;
}
__device__ __forceinline__ uint32_t smem_u32(const void* p) {
    uint32_t a;
    asm("{ .reg .u64 t; cvta.to.shared.u64 t, %1; cvt.u32.u64 %0, t; }" : "=r"(a) : "l"(p));
    return a;
}
__device__ __forceinline__ void cp16(uint32_t dst, const void* src) {
    asm volatile("cp.async.cg.shared.global [%0], [%1], 16;" :: "r"(dst), "l"(src) : "memory");
}
__device__ __forceinline__ void mma_tf32(float c[4],
                                         unsigned a0, unsigned a1, unsigned a2, unsigned a3,
                                         unsigned b0, unsigned b1) {
    asm volatile(
        "mma.sync.aligned.m16n8k8.row.col.f32.tf32.tf32.f32 "
        "{%0,%1,%2,%3}, {%4,%5,%6,%7}, {%8,%9}, {%0,%1,%2,%3};"
        : "+f"(c[0]), "+f"(c[1]), "+f"(c[2]), "+f"(c[3])
        : "r"(a0), "r"(a1), "r"(a2), "r"(a3), "r"(b0), "r"(b1));
}

// ---------------- init ----------------
__global__ void init_kernel(float* __restrict__ out) {
    size_t n = (size_t)Tdim * Hdim;
    for (size_t i = (size_t)blockIdx.x * blockDim.x + threadIdx.x; i < n;
         i += (size_t)gridDim.x * blockDim.x)
        out[i] = 0.0f;
    if (blockIdx.x == 0 && threadIdx.x < Edim) {
        d_counts[threadIdx.x] = 0;
        d_cursor[threadIdx.x] = 0;
    }
}

// ---------------- RMSNorm + router + top-2 ----------------
__global__ __launch_bounds__(256) void routing_kernel(const float* __restrict__ x,
                                                      const float* __restrict__ nw,
                                                      const float* __restrict__ rw) {
    int t = blockIdx.x, tid = threadIdx.x, lane = tid & 31, warp = tid >> 5;
    const float* xr = x + (size_t)t * Hdim;
    __shared__ float sred[8];
    __shared__ float slog[8][9];
    __shared__ float s_rms;

    float ss = 0.0f;
    for (int i = tid; i < Hdim; i += 256) { float v = xr[i]; ss += v * v; }
    ss = warpsum(ss);
    if (lane == 0) sred[warp] = ss;
    __syncthreads();
    if (tid == 0) {
        float tot = 0.0f;
        for (int w = 0; w < 8; w++) tot += sred[w];
        s_rms = rsqrtf(tot / (float)Hdim + 1e-6f);
    }
    __syncthreads();
    float rms = s_rms;

    float acc[8];
#pragma unroll
    for (int e = 0; e < 8; e++) acc[e] = 0.0f;
    for (int i = tid; i < Hdim; i += 256) {
        float tv = xr[i] * rms * nw[i];
        // tf32-round for the tensor GEMMs; full precision feeds the router
        d_tn[(size_t)t * Hdim + i] = __uint_as_float(f2tf(tv));
#pragma unroll
        for (int e = 0; e < 8; e++) acc[e] += tv * rw[i * Edim + e];
    }
#pragma unroll
    for (int e = 0; e < 8; e++) {
        float v = warpsum(acc[e]);
        if (lane == 0) slog[warp][e] = v;
    }
    __syncthreads();
    if (tid == 0) {
        float lg[8];
        for (int e = 0; e < 8; e++) {
            float s = 0.0f;
            for (int w = 0; w < 8; w++) s += slog[w][e];
            lg[e] = s;
        }
        float mx = lg[0];
        for (int e = 1; e < 8; e++) mx = fmaxf(mx, lg[e]);
        float af[8], sum = 0.0f;
        for (int e = 0; e < 8; e++) { af[e] = expf(lg[e] - mx); sum += af[e]; }
        float inv = 1.0f / sum;
        for (int e = 0; e < 8; e++) af[e] *= inv;
        int i1 = 0;
        for (int e = 1; e < 8; e++) if (af[e] > af[i1]) i1 = e;
        int i2 = (i1 == 0) ? 1 : 0;
        for (int e = 0; e < 8; e++) if (e != i1 && af[e] > af[i2]) i2 = e;
        float v1 = af[i1], v2 = af[i2], s2 = v1 + v2;
        d_topi[2 * t] = i1;  d_topi[2 * t + 1] = i2;
        d_topw[2 * t] = v1 / s2;  d_topw[2 * t + 1] = v2 / s2;
        atomicAdd(&d_counts[i1], 1);
        atomicAdd(&d_counts[i2], 1);
    }
}

__global__ void scan_kernel() {
    if (threadIdx.x == 0) {
        int o = 0;
        for (int e = 0; e < Edim; e++) { d_offsets[e] = o; o += d_counts[e]; }
        d_offsets[Edim] = o;
    }
}

__global__ void assign_kernel() {
    int t = blockIdx.x * blockDim.x + threadIdx.x;
    if (t >= Tdim) return;
    for (int k = 0; k < 2; k++) {
        int e = d_topi[2 * t + k];
        int p = d_offsets[e] + atomicAdd(&d_cursor[e], 1);
        d_rows[p] = t;
        d_wgt[p] = d_topw[2 * t + k];
    }
}

// ---------------- grouped GEMM, legacy tf32 mma.sync, 3-stage cp.async ----------------
// CTA tile 128x128, BK=32, 8 warps (2m x 4n), warp tile 64x32 per matrix.
// MODE 0: fused gate+up (+silu epilogue -> d_h).  N=Idim, K=Hdim, 2 B-matrices.
// MODE 1: down (atomic weighted scatter -> out).  N=Hdim, K=Idim, 1 B-matrix.
// SMEM per stage: A = 128 rows x 128B (sw128 swizzled) = 16384B
//                 B per matrix = 32 k-rows x 544B (128 n-floats + 8 pad) = 17408B

#define BPITCH 544

template <int MODE>
__global__ __launch_bounds__(256, 1) void mma_gemm(const float* __restrict__ W0,
                                                   const float* __restrict__ W1,
                                                   float* __restrict__ Out) {
    constexpr int NDIM = (MODE == 1) ? Hdim : Idim;
    constexpr int KDIM = (MODE == 1) ? Idim : Hdim;
    constexpr int NMAT = (MODE == 1) ? 1 : 2;
    constexpr int NK = KDIM / 32;
    constexpr int STAGE = 16384 + NMAT * 17408;

    const int e = blockIdx.z;
    const int cnt = d_counts[e];
    const int m0 = blockIdx.x * 128;
    if (m0 >= cnt) return;
    const int base = d_offsets[e];
    const int n0 = blockIdx.y * 128;
    const int valid = cnt - m0;

    extern __shared__ char smem[];
    const uint32_t sb = smem_u32(smem);
    const int tid = threadIdx.x, wid = tid >> 5, lane = tid & 31;
    const int wm = wid & 1, wn = wid >> 1;

    int*   tokS = (int*)(smem + 3 * STAGE);
    float* wgtS = (float*)(smem + 3 * STAGE + 512);
    if (tid < 128) {
        int slot = base + m0 + min(tid, valid - 1);
        tokS[tid] = d_rows[slot];
        wgtS[tid] = d_wgt[slot];
    }
    __syncthreads();

    // per-thread cp.async source rows / dst offsets for A (4 rows, stride 32)
    const float* arow[4];
    uint32_t adst[4];
    {
        int seg = tid & 7;
#pragma unroll
        for (int j = 0; j < 4; j++) {
            int r = j * 32 + (tid >> 3);
            int rc = min(r, valid - 1);
            if (MODE == 0) arow[j] = d_tn + (size_t)tokS[rc] * KDIM + seg * 4;
            else           arow[j] = d_h  + (size_t)(base + m0 + rc) * KDIM + seg * 4;
            uint32_t o = (uint32_t)(r * 128 + seg * 16);
            adst[j] = o ^ ((o >> 3) & 0x70);
        }
    }
    const float* Wsrc[2];
    Wsrc[0] = W0 + (size_t)e * KDIM * NDIM + n0 + lane * 4;
    Wsrc[1] = (NMAT == 2) ? (W1 + (size_t)e * KDIM * NDIM + n0 + lane * 4) : W0;

    auto load_stage = [&](int kc, int buf) {
        uint32_t ab = sb + buf * STAGE;
        const int k0 = kc * 32;
#pragma unroll
        for (int j = 0; j < 4; j++) cp16(ab + adst[j], arow[j] + k0);
#pragma unroll
        for (int m = 0; m < NMAT; m++) {
            uint32_t bb = ab + 16384 + m * 17408;
#pragma unroll
            for (int j = 0; j < 4; j++) {
                int kk = j * 8 + wid;
                cp16(bb + kk * BPITCH + lane * 16, Wsrc[m] + (size_t)(k0 + kk) * NDIM);
            }
        }
        asm volatile("cp.async.commit_group;" ::: "memory");
    };

    float acc[NMAT][4][4][4];
#pragma unroll
    for (int m = 0; m < NMAT; m++)
#pragma unroll
        for (int mf = 0; mf < 4; mf++)
#pragma unroll
            for (int nf = 0; nf < 4; nf++)
#pragma unroll
                for (int q = 0; q < 4; q++) acc[m][mf][nf][q] = 0.0f;

    load_stage(0, 0);
    if (NK > 1) load_stage(1, 1);

    const int kl = lane & 3;
    const int qid = lane >> 2;

#pragma unroll 1
    for (int kc = 0; kc < NK; kc++) {
        if (kc + 2 < NK) load_stage(kc + 2, (kc + 2) % 3);
        if (kc + 2 < NK)      asm volatile("cp.async.wait_group 2;" ::: "memory");
        else if (kc + 1 < NK) asm volatile("cp.async.wait_group 1;" ::: "memory");
        else                  asm volatile("cp.async.wait_group 0;" ::: "memory");
        __syncthreads();

        const char* Ab = smem + (kc % 3) * STAGE;
#pragma unroll
        for (int ks = 0; ks < 32; ks += 8) {
            unsigned a[4][4];
#pragma unroll
            for (int mf = 0; mf < 4; mf++) {
                int r = wm * 64 + mf * 16 + qid;
                int xr = (r & 7) << 4;
                int ro = r * 128;
                a[mf][0] = *(const unsigned*)(Ab + ro +        (((ks + kl) * 4) ^ xr));
                a[mf][1] = *(const unsigned*)(Ab + ro + 1024 + (((ks + kl) * 4) ^ xr));
                a[mf][2] = *(const unsigned*)(Ab + ro +        (((ks + kl + 4) * 4) ^ xr));
                a[mf][3] = *(const unsigned*)(Ab + ro + 1024 + (((ks + kl + 4) * 4) ^ xr));
            }
#pragma unroll
            for (int m = 0; m < NMAT; m++) {
                const char* Bb = Ab + 16384 + m * 17408;
#pragma unroll
                for (int nf = 0; nf < 4; nf++) {
                    int c = wn * 32 + nf * 8 + qid;
                    unsigned b0 = f2tf(*(const float*)(Bb + (ks + kl) * BPITCH + c * 4));
                    unsigned b1 = f2tf(*(const float*)(Bb + (ks + kl + 4) * BPITCH + c * 4));
#pragma unroll
                    for (int mf = 0; mf < 4; mf++)
                        mma_tf32(acc[m][mf][nf], a[mf][0], a[mf][1], a[mf][2], a[mf][3], b0, b1);
                }
            }
        }
        __syncthreads();
    }

    // ---------------- epilogue ----------------
#pragma unroll
    for (int mf = 0; mf < 4; mf++) {
#pragma unroll
        for (int half = 0; half < 2; half++) {
            int r = wm * 64 + mf * 16 + qid + half * 8;
            if (r >= valid) continue;
#pragma unroll
            for (int nf = 0; nf < 4; nf++) {
                int col = n0 + wn * 32 + nf * 8 + kl * 2;
                if (MODE == 0) {
                    float g0 = acc[0][mf][nf][half * 2 + 0];
                    float g1 = acc[0][mf][nf][half * 2 + 1];
                    float u0 = acc[1][mf][nf][half * 2 + 0];
                    float u1 = acc[1][mf][nf][half * 2 + 1];
                    float h0 = g0 / (1.0f + expf(-g0)) * u0;
                    float h1 = g1 / (1.0f + expf(-g1)) * u1;
                    float2 v = make_float2(__uint_as_float(f2tf(h0)),
                                           __uint_as_float(f2tf(h1)));
                    *(float2*)(d_h + (size_t)(base + m0 + r) * Idim + col) = v;
                } else {
                    int tok = tokS[r];
                    float w = wgtS[r];
                    float* dst = Out + (size_t)tok * Hdim + col;
                    atomicAdd(dst + 0, w * acc[0][mf][nf][half * 2 + 0]);
                    atomicAdd(dst + 1, w * acc[0][mf][nf][half * 2 + 1]);
                }
            }
        }
    }
}

// ---------------- launch ----------------
extern "C" void kernel_launch(void* const* d_in, const int* in_sizes, int n_in,
                              void* d_out, int out_size) {
    const float* x  = (const float*)d_in[0];
    const float* nw = (const float*)d_in[1];
    const float* rw = (const float*)d_in[2];
    const float* wg = (const float*)d_in[3];
    const float* wu = (const float*)d_in[4];
    const float* wd = (const float*)d_in[5];
    float* out = (float*)d_out;

    constexpr int SMEM_GU = 3 * (16384 + 2 * 17408) + 1024;  // 154624
    constexpr int SMEM_DN = 3 * (16384 + 1 * 17408) + 1024;  // 102400
    static bool attr_done = false;
    if (!attr_done) {
        cudaFuncSetAttribute(mma_gemm<0>, cudaFuncAttributeMaxDynamicSharedMemorySize, SMEM_GU);
        cudaFuncSetAttribute(mma_gemm<1>, cudaFuncAttributeMaxDynamicSharedMemorySize, SMEM_DN);
        attr_done = true;
    }

    init_kernel<<<512, 256>>>(out);
    routing_kernel<<<Tdim, 256>>>(x, nw, rw);
    scan_kernel<<<1, 32>>>();
    assign_kernel<<<Tdim / 256, 256>>>();

    // x = row-tile (fastest -> same-B CTAs concurrent), y = n-tile, z = expert
    dim3 g1(TK / 128, Idim / 128, Edim);   // 32 x 32 x 8, most x exit early
    mma_gemm<0><<<g1, 256, SMEM_GU>>>(wg, wu, nullptr);

    dim3 g2(TK / 128, Hdim / 128, Edim);   // 32 x 16 x 8
    mma_gemm<1><<<g2, 256, SMEM_DN>>>(wd, nullptr, out);
}

// round 5
// speedup vs baseline: 4.6160x; 1.0570x over previous
#include <cuda_runtime.h>
#include <math.h>
#include <stdint.h>

#define Hdim 2048
#define Idim 4096
#define Edim 8
#define Tdim 2048
#define TK   4096   // T * K slots (always exact: every token picks 2 experts)

// ---------------- scratch (static device arrays; no allocations) ----------------
__device__ float d_tn[(size_t)Tdim * Hdim];   // normalized tokens (tf32-rounded)
__device__ float d_g[(size_t)TK * Idim];      // gate proj
__device__ float d_u[(size_t)TK * Idim];      // up proj
__device__ float d_h[(size_t)TK * Idim];      // silu(g)*u (tf32-rounded)
__device__ int   d_rows[TK];
__device__ float d_wgt[TK];
__device__ int   d_topi[Tdim * 2];
__device__ float d_topw[Tdim * 2];
__device__ int   d_counts[Edim];
__device__ int   d_cursor[Edim];
__device__ int   d_offsets[Edim + 1];

// ---------------- helpers ----------------
__device__ __forceinline__ float warpsum(float v) {
#pragma unroll
    for (int o = 16; o > 0; o >>= 1) v += __shfl_down_sync(0xFFFFFFFFu, v, o);
    return v;
}
__device__ __forceinline__ unsigned f2tf(float x) {
    unsigned u;
    asm("cvt.rna.tf32.f32 %0, %1;" : "=r"(u) : "f"(x));
    return u;
}
__device__ __forceinline__ uint32_t smem_u32(const void* p) {
    uint32_t a;
    asm("{ .reg .u64 t; cvta.to.shared.u64 t, %1; cvt.u32.u64 %0, t; }" : "=r"(a) : "l"(p));
    return a;
}
__device__ __forceinline__ void cp16(uint32_t dst, const void* src) {
    asm volatile("cp.async.cg.shared.global [%0], [%1], 16;" :: "r"(dst), "l"(src) : "memory");
}
__device__ __forceinline__ void mma_tf32(float c[4],
                                         unsigned a0, unsigned a1, unsigned a2, unsigned a3,
                                         unsigned b0, unsigned b1) {
    asm volatile(
        "mma.sync.aligned.m16n8k8.row.col.f32.tf32.tf32.f32 "
        "{%0,%1,%2,%3}, {%4,%5,%6,%7}, {%8,%9}, {%0,%1,%2,%3};"
        : "+f"(c[0]), "+f"(c[1]), "+f"(c[2]), "+f"(c[3])
        : "r"(a0), "r"(a1), "r"(a2), "r"(a3), "r"(b0), "r"(b1));
}

// ---------------- init ----------------
__global__ void init_kernel(float* __restrict__ out) {
    size_t n = (size_t)Tdim * Hdim;
    for (size_t i = (size_t)blockIdx.x * blockDim.x + threadIdx.x; i < n;
         i += (size_t)gridDim.x * blockDim.x)
        out[i] = 0.0f;
    if (blockIdx.x == 0 && threadIdx.x < Edim) {
        d_counts[threadIdx.x] = 0;
        d_cursor[threadIdx.x] = 0;
    }
}

// ---------------- RMSNorm + router + top-2 ----------------
__global__ __launch_bounds__(256) void routing_kernel(const float* __restrict__ x,
                                                      const float* __restrict__ nw,
                                                      const float* __restrict__ rw) {
    int t = blockIdx.x, tid = threadIdx.x, lane = tid & 31, warp = tid >> 5;
    const float* xr = x + (size_t)t * Hdim;
    __shared__ float sred[8];
    __shared__ float slog[8][9];
    __shared__ float s_rms;

    float ss = 0.0f;
    for (int i = tid; i < Hdim; i += 256) { float v = xr[i]; ss += v * v; }
    ss = warpsum(ss);
    if (lane == 0) sred[warp] = ss;
    __syncthreads();
    if (tid == 0) {
        float tot = 0.0f;
        for (int w = 0; w < 8; w++) tot += sred[w];
        s_rms = rsqrtf(tot / (float)Hdim + 1e-6f);
    }
    __syncthreads();
    float rms = s_rms;

    float acc[8];
#pragma unroll
    for (int e = 0; e < 8; e++) acc[e] = 0.0f;
    for (int i = tid; i < Hdim; i += 256) {
        float tv = xr[i] * rms * nw[i];
        d_tn[(size_t)t * Hdim + i] = __uint_as_float(f2tf(tv));
#pragma unroll
        for (int e = 0; e < 8; e++) acc[e] += tv * rw[i * Edim + e];
    }
#pragma unroll
    for (int e = 0; e < 8; e++) {
        float v = warpsum(acc[e]);
        if (lane == 0) slog[warp][e] = v;
    }
    __syncthreads();
    if (tid == 0) {
        float lg[8];
        for (int e = 0; e < 8; e++) {
            float s = 0.0f;
            for (int w = 0; w < 8; w++) s += slog[w][e];
            lg[e] = s;
        }
        float mx = lg[0];
        for (int e = 1; e < 8; e++) mx = fmaxf(mx, lg[e]);
        float af[8], sum = 0.0f;
        for (int e = 0; e < 8; e++) { af[e] = expf(lg[e] - mx); sum += af[e]; }
        float inv = 1.0f / sum;
        for (int e = 0; e < 8; e++) af[e] *= inv;
        int i1 = 0;
        for (int e = 1; e < 8; e++) if (af[e] > af[i1]) i1 = e;
        int i2 = (i1 == 0) ? 1 : 0;
        for (int e = 0; e < 8; e++) if (e != i1 && af[e] > af[i2]) i2 = e;
        float v1 = af[i1], v2 = af[i2], s2 = v1 + v2;
        d_topi[2 * t] = i1;  d_topi[2 * t + 1] = i2;
        d_topw[2 * t] = v1 / s2;  d_topw[2 * t + 1] = v2 / s2;
        atomicAdd(&d_counts[i1], 1);
        atomicAdd(&d_counts[i2], 1);
    }
}

__global__ void scan_kernel() {
    if (threadIdx.x == 0) {
        int o = 0;
        for (int e = 0; e < Edim; e++) { d_offsets[e] = o; o += d_counts[e]; }
        d_offsets[Edim] = o;
    }
}

__global__ void assign_kernel() {
    int t = blockIdx.x * blockDim.x + threadIdx.x;
    if (t >= Tdim) return;
    for (int k = 0; k < 2; k++) {
        int e = d_topi[2 * t + k];
        int p = d_offsets[e] + atomicAdd(&d_cursor[e], 1);
        d_rows[p] = t;
        d_wgt[p] = d_topw[2 * t + k];
    }
}

// ---------------- grouped GEMM, tf32 mma.sync, 3-stage cp.async, 2 CTA/SM ----------------
// CTA tile 128x128, BK=32, 8 warps (2m x 4n), warp tile 64x32, single B matrix.
// MODE 0: projection (A = gathered d_tn, plain store to d_g/d_u per z&1). N=Idim, K=Hdim.
// MODE 1: down (A = d_h rows, atomic weighted scatter -> out).            N=Hdim, K=Idim.
// SMEM/stage: A = 128 rows x 128B (swizzled) = 16384B; B = 32 x 544B = 17408B.

#define BPITCH 544
#define STAGE  33792
#define SMEM_TOT (3 * STAGE + 1024)   // 102400 -> 2 CTAs/SM

template <int MODE>
__global__ __launch_bounds__(256, 2) void mma_gemm(const float* __restrict__ W0,
                                                   const float* __restrict__ W1,
                                                   float* __restrict__ Out) {
    constexpr int NDIM = (MODE == 1) ? Hdim : Idim;
    constexpr int KDIM = (MODE == 1) ? Idim : Hdim;
    constexpr int NK = KDIM / 32;

    const int zz = blockIdx.z;
    const int e = (MODE == 0) ? (zz >> 1) : zz;
    const int cnt = d_counts[e];
    const int m0 = blockIdx.x * 128;
    if (m0 >= cnt) return;
    const int base = d_offsets[e];
    const int n0 = blockIdx.y * 128;
    const int valid = cnt - m0;

    const float* W = (MODE == 0) ? ((zz & 1) ? W1 : W0) : W0;
    float* Dst = (MODE == 0) ? (((zz & 1) ? d_u : d_g)) : Out;

    extern __shared__ char smem[];
    const uint32_t sb = smem_u32(smem);
    const int tid = threadIdx.x, wid = tid >> 5, lane = tid & 31;
    const int wm = wid & 1, wn = wid >> 1;

    int*   tokS = (int*)(smem + 3 * STAGE);
    float* wgtS = (float*)(smem + 3 * STAGE + 512);
    if (tid < 128) {
        int slot = base + m0 + min(tid, valid - 1);
        tokS[tid] = d_rows[slot];
        wgtS[tid] = d_wgt[slot];
    }
    __syncthreads();

    // per-thread cp.async A sources (4 rows, stride 32) and swizzled dsts
    const float* arow[4];
    uint32_t adst[4];
    {
        int seg = tid & 7;
#pragma unroll
        for (int j = 0; j < 4; j++) {
            int r = j * 32 + (tid >> 3);
            int rc = min(r, valid - 1);
            if (MODE == 0) arow[j] = d_tn + (size_t)tokS[rc] * KDIM + seg * 4;
            else           arow[j] = d_h  + (size_t)(base + m0 + rc) * KDIM + seg * 4;
            uint32_t o = (uint32_t)(r * 128 + seg * 16);
            adst[j] = o ^ ((o >> 3) & 0x70);
        }
    }
    const float* Wsrc = W + (size_t)e * KDIM * NDIM + n0 + lane * 4;

    auto load_stage = [&](int kc, int buf) {
        uint32_t ab = sb + buf * STAGE;
        const int k0 = kc * 32;
#pragma unroll
        for (int j = 0; j < 4; j++) cp16(ab + adst[j], arow[j] + k0);
        uint32_t bb = ab + 16384;
#pragma unroll
        for (int j = 0; j < 4; j++) {
            int kk = j * 8 + wid;
            cp16(bb + kk * BPITCH + lane * 16, Wsrc + (size_t)(k0 + kk) * NDIM);
        }
        asm volatile("cp.async.commit_group;" ::: "memory");
    };

    float acc[4][4][4];
#pragma unroll
    for (int mf = 0; mf < 4; mf++)
#pragma unroll
        for (int nf = 0; nf < 4; nf++)
#pragma unroll
            for (int q = 0; q < 4; q++) acc[mf][nf][q] = 0.0f;

    load_stage(0, 0);
    load_stage(1, 1);

    const int kl = lane & 3;
    const int qid = lane >> 2;

#pragma unroll 1
    for (int kc = 0; kc < NK; kc++) {
        if (kc + 2 < NK) load_stage(kc + 2, (kc + 2) % 3);
        if (kc + 2 < NK)      asm volatile("cp.async.wait_group 2;" ::: "memory");
        else if (kc + 1 < NK) asm volatile("cp.async.wait_group 1;" ::: "memory");
        else                  asm volatile("cp.async.wait_group 0;" ::: "memory");
        __syncthreads();

        const char* Ab = smem + (kc % 3) * STAGE;
        const char* Bb = Ab + 16384;
#pragma unroll
        for (int ks = 0; ks < 32; ks += 8) {
            unsigned a[4][4];
#pragma unroll
            for (int mf = 0; mf < 4; mf++) {
                int r = wm * 64 + mf * 16 + qid;
                int xr = (r & 7) << 4;
                int ro = r * 128;
                a[mf][0] = *(const unsigned*)(Ab + ro +        (((ks + kl) * 4) ^ xr));
                a[mf][1] = *(const unsigned*)(Ab + ro + 1024 + (((ks + kl) * 4) ^ xr));
                a[mf][2] = *(const unsigned*)(Ab + ro +        (((ks + kl + 4) * 4) ^ xr));
                a[mf][3] = *(const unsigned*)(Ab + ro + 1024 + (((ks + kl + 4) * 4) ^ xr));
            }
#pragma unroll
            for (int nf = 0; nf < 4; nf++) {
                int c = wn * 32 + nf * 8 + qid;
                unsigned b0 = f2tf(*(const float*)(Bb + (ks + kl) * BPITCH + c * 4));
                unsigned b1 = f2tf(*(const float*)(Bb + (ks + kl + 4) * BPITCH + c * 4));
#pragma unroll
                for (int mf = 0; mf < 4; mf++)
                    mma_tf32(acc[mf][nf], a[mf][0], a[mf][1], a[mf][2], a[mf][3], b0, b1);
            }
        }
        __syncthreads();
    }

    // ---------------- epilogue ----------------
#pragma unroll
    for (int mf = 0; mf < 4; mf++) {
#pragma unroll
        for (int half = 0; half < 2; half++) {
            int r = wm * 64 + mf * 16 + qid + half * 8;
            if (r >= valid) continue;
#pragma unroll
            for (int nf = 0; nf < 4; nf++) {
                int col = n0 + wn * 32 + nf * 8 + kl * 2;
                float v0 = acc[mf][nf][half * 2 + 0];
                float v1 = acc[mf][nf][half * 2 + 1];
                if (MODE == 0) {
                    *(float2*)(Dst + (size_t)(base + m0 + r) * Idim + col) =
                        make_float2(v0, v1);
                } else {
                    int tok = tokS[r];
                    float w = wgtS[r];
                    float* dst = Dst + (size_t)tok * Hdim + col;
                    atomicAdd(dst + 0, w * v0);
                    atomicAdd(dst + 1, w * v1);
                }
            }
        }
    }
}

// ---------------- h = silu(g) * u (tf32-rounded for the down GEMM) ----------------
__global__ void silu_kernel() {
    size_t n = (size_t)TK * Idim;
    for (size_t i = (size_t)blockIdx.x * blockDim.x + threadIdx.x; i < n;
         i += (size_t)gridDim.x * blockDim.x) {
        float g = d_g[i], u = d_u[i];
        float h = g / (1.0f + expf(-g)) * u;
        d_h[i] = __uint_as_float(f2tf(h));
    }
}

// ---------------- launch ----------------
extern "C" void kernel_launch(void* const* d_in, const int* in_sizes, int n_in,
                              void* d_out, int out_size) {
    const float* x  = (const float*)d_in[0];
    const float* nw = (const float*)d_in[1];
    const float* rw = (const float*)d_in[2];
    const float* wg = (const float*)d_in[3];
    const float* wu = (const float*)d_in[4];
    const float* wd = (const float*)d_in[5];
    float* out = (float*)d_out;

    static bool attr_done = false;
    if (!attr_done) {
        cudaFuncSetAttribute(mma_gemm<0>, cudaFuncAttributeMaxDynamicSharedMemorySize, SMEM_TOT);
        cudaFuncSetAttribute(mma_gemm<1>, cudaFuncAttributeMaxDynamicSharedMemorySize, SMEM_TOT);
        attr_done = true;
    }

    init_kernel<<<512, 256>>>(out);
    routing_kernel<<<Tdim, 256>>>(x, nw, rw);
    scan_kernel<<<1, 32>>>();
    assign_kernel<<<Tdim / 256, 256>>>();

    // gate+up in one launch: z = expert*2 + {0:gate, 1:up}
    dim3 g1(TK / 128, Idim / 128, Edim * 2);   // 32 x 32 x 16, most x exit early
    mma_gemm<0><<<g1, 256, SMEM_TOT>>>(wg, wu, nullptr);

    silu_kernel<<<2048, 256>>>();

    dim3 g2(TK / 128, Hdim / 128, Edim);       // 32 x 16 x 8
    mma_gemm<1><<<g2, 256, SMEM_TOT>>>(wd, nullptr, out);
}

// round 7
// speedup vs baseline: 6.4805x; 1.4039x over previous
#include <cuda_runtime.h>
#include <cuda_fp16.h>
#include <math.h>
#include <stdint.h>

#define Hdim 2048
#define Idim 4096
#define Edim 8
#define Tdim 2048
#define TK   4096   // T * K slots (always exact: every token picks 2 experts)

// ---------------- scratch (static device arrays; no allocations) ----------------
__device__ __half d_tn[(size_t)Tdim * Hdim];  // normalized tokens (fp16)
__device__ float  d_g[(size_t)TK * Idim];     // gate proj (fp32)
__device__ float  d_u[(size_t)TK * Idim];     // up proj (fp32)
__device__ __half d_h[(size_t)TK * Idim];     // silu(g)*u (fp16)
__device__ int    d_rows[TK];
__device__ float  d_wgt[TK];
__device__ int    d_topi[Tdim * 2];
__device__ float  d_topw[Tdim * 2];
__device__ int    d_counts[Edim];
__device__ int    d_cursor[Edim];
__device__ int    d_offsets[Edim + 1];

// ---------------- helpers ----------------
__device__ __forceinline__ float warpsum(float v) {
#pragma unroll
    for (int o = 16; o > 0; o >>= 1) v += __shfl_down_sync(0xFFFFFFFFu, v, o);
    return v;
}
__device__ __forceinline__ uint32_t smem_u32(const void* p) {
    uint32_t a;
    asm("{ .reg .u64 t; cvta.to.shared.u64 t, %1; cvt.u32.u64 %0, t; }" : "=r"(a) : "l"(p));
    return a;
}
__device__ __forceinline__ void cp16(uint32_t dst, const void* src) {
    asm volatile("cp.async.cg.shared.global [%0], [%1], 16;" :: "r"(dst), "l"(src) : "memory");
}
__device__ __forceinline__ unsigned pack2h(float lo, float hi) {
    __half2 h = __floats2half2_rn(lo, hi);   // .x (lo) in low 16 bits
    return *reinterpret_cast<unsigned*>(&h);
}
__device__ __forceinline__ void mma_f16(float c[4], const unsigned a[4],
                                        unsigned b0, unsigned b1) {
    asm volatile(
        "mma.sync.aligned.m16n8k16.row.col.f32.f16.f16.f32 "
        "{%0,%1,%2,%3}, {%4,%5,%6,%7}, {%8,%9}, {%0,%1,%2,%3};"
        : "+f"(c[0]), "+f"(c[1]), "+f"(c[2]), "+f"(c[3])
        : "r"(a[0]), "r"(a[1]), "r"(a[2]), "r"(a[3]), "r"(b0), "r"(b1));
}
__device__ __forceinline__ void ldsm4(unsigned r[4], uint32_t addr) {
    asm volatile("ldmatrix.sync.aligned.m8n8.x4.shared.b16 {%0,%1,%2,%3}, [%4];"
                 : "=r"(r[0]), "=r"(r[1]), "=r"(r[2]), "=r"(r[3]) : "r"(addr));
}

// ---------------- init ----------------
__global__ void init_kernel(float* __restrict__ out) {
    size_t n = (size_t)Tdim * Hdim;
    for (size_t i = (size_t)blockIdx.x * blockDim.x + threadIdx.x; i < n;
         i += (size_t)gridDim.x * blockDim.x)
        out[i] = 0.0f;
    if (blockIdx.x == 0 && threadIdx.x < Edim) {
        d_counts[threadIdx.x] = 0;
        d_cursor[threadIdx.x] = 0;
    }
}

// ---------------- RMSNorm + router + top-2 ----------------
__global__ __launch_bounds__(256) void routing_kernel(const float* __restrict__ x,
                                                      const float* __restrict__ nw,
                                                      const float* __restrict__ rw) {
    int t = blockIdx.x, tid = threadIdx.x, lane = tid & 31, warp = tid >> 5;
    const float* xr = x + (size_t)t * Hdim;
    __shared__ float sred[8];
    __shared__ float slog[8][9];
    __shared__ float s_rms;

    float ss = 0.0f;
    for (int i = tid; i < Hdim; i += 256) { float v = xr[i]; ss += v * v; }
    ss = warpsum(ss);
    if (lane == 0) sred[warp] = ss;
    __syncthreads();
    if (tid == 0) {
        float tot = 0.0f;
        for (int w = 0; w < 8; w++) tot += sred[w];
        s_rms = rsqrtf(tot / (float)Hdim + 1e-6f);
    }
    __syncthreads();
    float rms = s_rms;

    float acc[8];
#pragma unroll
    for (int e = 0; e < 8; e++) acc[e] = 0.0f;
    for (int i = tid; i < Hdim; i += 256) {
        float tv = xr[i] * rms * nw[i];
        d_tn[(size_t)t * Hdim + i] = __float2half_rn(tv);
#pragma unroll
        for (int e = 0; e < 8; e++) acc[e] += tv * rw[i * Edim + e];
    }
#pragma unroll
    for (int e = 0; e < 8; e++) {
        float v = warpsum(acc[e]);
        if (lane == 0) slog[warp][e] = v;
    }
    __syncthreads();
    if (tid == 0) {
        float lg[8];
        for (int e = 0; e < 8; e++) {
            float s = 0.0f;
            for (int w = 0; w < 8; w++) s += slog[w][e];
            lg[e] = s;
        }
        float mx = lg[0];
        for (int e = 1; e < 8; e++) mx = fmaxf(mx, lg[e]);
        float af[8], sum = 0.0f;
        for (int e = 0; e < 8; e++) { af[e] = expf(lg[e] - mx); sum += af[e]; }
        float inv = 1.0f / sum;
        for (int e = 0; e < 8; e++) af[e] *= inv;
        int i1 = 0;
        for (int e = 1; e < 8; e++) if (af[e] > af[i1]) i1 = e;
        int i2 = (i1 == 0) ? 1 : 0;
        for (int e = 0; e < 8; e++) if (e != i1 && af[e] > af[i2]) i2 = e;
        float v1 = af[i1], v2 = af[i2], s2 = v1 + v2;
        d_topi[2 * t] = i1;  d_topi[2 * t + 1] = i2;
        d_topw[2 * t] = v1 / s2;  d_topw[2 * t + 1] = v2 / s2;
        atomicAdd(&d_counts[i1], 1);
        atomicAdd(&d_counts[i2], 1);
    }
}

__global__ void scan_kernel() {
    if (threadIdx.x == 0) {
        int o = 0;
        for (int e = 0; e < Edim; e++) { d_offsets[e] = o; o += d_counts[e]; }
        d_offsets[Edim] = o;
    }
}

__global__ void assign_kernel() {
    int t = blockIdx.x * blockDim.x + threadIdx.x;
    if (t >= Tdim) return;
    for (int k = 0; k < 2; k++) {
        int e = d_topi[2 * t + k];
        int p = d_offsets[e] + atomicAdd(&d_cursor[e], 1);
        d_rows[p] = t;
        d_wgt[p] = d_topw[2 * t + k];
    }
}

// ---------------- grouped GEMM, fp16 m16n8k16, 4-stage cp.async, 2 CTA/SM ----------------
// CTA tile 128x128, BK=32, 8 warps (2m x 4n), warp tile 64x32.
// A in SMEM: fp16, 128 rows x 64B, granule-swizzled (g ^= (r>>1)&3), read via ldmatrix.x4.
// B in SMEM: fp32 [k][n], pitch 528B, converted to fp16 in registers.
// MODE 0: projection (A = gathered d_tn -> d_g/d_u per z&1). N=Idim, K=Hdim.
// MODE 1: down (A = d_h rows, atomic weighted scatter -> out). N=Hdim, K=Idim.

#define BPH   528
#define ASTG  8192
#define STG   (ASTG + 32 * BPH)       // 25088
#define NSTG  4
#define SMEM_TOT (NSTG * STG + 1024)  // 101376 -> 2 CTAs/SM

template <int MODE>
__global__ __launch_bounds__(256, 2) void mma_gemm(const float* __restrict__ W0,
                                                   const float* __restrict__ W1,
                                                   float* __restrict__ Out) {
    constexpr int NDIM = (MODE == 1) ? Hdim : Idim;
    constexpr int KDIM = (MODE == 1) ? Idim : Hdim;
    constexpr int NK = KDIM / 32;

    const int zz = blockIdx.z;
    const int e = (MODE == 0) ? (zz >> 1) : zz;
    const int cnt = d_counts[e];
    const int m0 = blockIdx.x * 128;
    if (m0 >= cnt) return;
    const int base = d_offsets[e];
    const int n0 = blockIdx.y * 128;
    const int valid = cnt - m0;

    const float* W = (MODE == 0) ? ((zz & 1) ? W1 : W0) : W0;
    float* Dst = (MODE == 0) ? (((zz & 1) ? d_u : d_g)) : Out;

    extern __shared__ char smem[];
    const uint32_t sb = smem_u32(smem);
    const int tid = threadIdx.x, wid = tid >> 5, lane = tid & 31;
    const int wm = wid & 1, wn = wid >> 1;
    const int qid = lane >> 2, kl = lane & 3;

    int*   tokS = (int*)(smem + NSTG * STG);
    float* wgtS = (float*)(smem + NSTG * STG + 512);
    if (tid < 128) {
        int slot = base + m0 + min(tid, valid - 1);
        tokS[tid] = d_rows[slot];
        wgtS[tid] = d_wgt[slot];
    }
    __syncthreads();

    // ---- A staging: each thread copies 2 granules (rows r0, r0+64; k-group g) ----
    const int r0 = tid >> 2, gA = tid & 3;
    const __half* arow0;
    const __half* arow1;
    if (MODE == 0) {
        arow0 = d_tn + (size_t)tokS[min(r0, valid - 1)] * KDIM + gA * 8;
        arow1 = d_tn + (size_t)tokS[min(r0 + 64, valid - 1)] * KDIM + gA * 8;
    } else {
        arow0 = d_h + (size_t)(base + m0 + min(r0, valid - 1)) * KDIM + gA * 8;
        arow1 = d_h + (size_t)(base + m0 + min(r0 + 64, valid - 1)) * KDIM + gA * 8;
    }
    const uint32_t sw = (gA ^ ((r0 >> 1) & 3)) * 16;   // same for r0 and r0+64
    const uint32_t adst0 = r0 * 64 + sw;
    const uint32_t adst1 = (r0 + 64) * 64 + sw;

    const float* Wsrc = W + (size_t)e * KDIM * NDIM + n0 + lane * 4;

    auto load_stage = [&](int kc, int buf) {
        uint32_t ab = sb + buf * STG;
        const int k0 = kc * 32;
        cp16(ab + adst0, arow0 + k0);
        cp16(ab + adst1, arow1 + k0);
        uint32_t bb = ab + ASTG;
#pragma unroll
        for (int j = 0; j < 4; j++) {
            int kk = j * 8 + wid;
            cp16(bb + kk * BPH + lane * 16, Wsrc + (size_t)(k0 + kk) * NDIM);
        }
        asm volatile("cp.async.commit_group;" ::: "memory");
    };

    // ---- ldmatrix per-lane address pieces ----
    const int t8 = lane >> 3;
    const int gt = t8 >> 1;                        // k-granule within ks16
    const int rL = (t8 & 1) * 8 + (lane & 7);      // row within 16-row frag
    uint32_t r64[4], swm[4];
#pragma unroll
    for (int mf = 0; mf < 4; mf++) {
        int r = wm * 64 + mf * 16 + rL;
        r64[mf] = r * 64;
        swm[mf] = (r >> 1) & 3;
    }

    float acc[4][4][4];
#pragma unroll
    for (int mf = 0; mf < 4; mf++)
#pragma unroll
        for (int nf = 0; nf < 4; nf++)
#pragma unroll
            for (int q = 0; q < 4; q++) acc[mf][nf][q] = 0.0f;

    load_stage(0, 0);
    load_stage(1, 1);
    load_stage(2, 2);

#pragma unroll 1
    for (int kc = 0; kc < NK; kc++) {
        if (kc < NK - 2)       asm volatile("cp.async.wait_group 2;" ::: "memory");
        else if (kc == NK - 2) asm volatile("cp.async.wait_group 1;" ::: "memory");
        else                   asm volatile("cp.async.wait_group 0;" ::: "memory");
        __syncthreads();
        if (kc + 3 < NK) load_stage(kc + 3, (kc + 3) & 3);

        const uint32_t Abase = sb + (kc & 3) * STG;
        const char* Bb = smem + (kc & 3) * STG + ASTG;
#pragma unroll
        for (int ks16 = 0; ks16 < 2; ks16++) {
            unsigned a[4][4];
#pragma unroll
            for (int mf = 0; mf < 4; mf++)
                ldsm4(a[mf], Abase + r64[mf] + (((ks16 * 2 + gt) ^ swm[mf]) << 4));
            const int ksr = ks16 * 16;
#pragma unroll
            for (int nf = 0; nf < 4; nf++) {
                const char* p = Bb + (wn * 32 + nf * 8 + qid) * 4;
                float b00 = *(const float*)(p + (ksr + 2 * kl) * BPH);
                float b01 = *(const float*)(p + (ksr + 2 * kl + 1) * BPH);
                float b10 = *(const float*)(p + (ksr + 2 * kl + 8) * BPH);
                float b11 = *(const float*)(p + (ksr + 2 * kl + 9) * BPH);
                unsigned b0 = pack2h(b00, b01);
                unsigned b1 = pack2h(b10, b11);
#pragma unroll
                for (int mf = 0; mf < 4; mf++)
                    mma_f16(acc[mf][nf], a[mf], b0, b1);
            }
        }
    }

    // ---------------- epilogue ----------------
#pragma unroll
    for (int mf = 0; mf < 4; mf++) {
#pragma unroll
        for (int half = 0; half < 2; half++) {
            int r = wm * 64 + mf * 16 + qid + half * 8;
            if (r >= valid) continue;
#pragma unroll
            for (int nf = 0; nf < 4; nf++) {
                int col = n0 + wn * 32 + nf * 8 + kl * 2;
                float v0 = acc[mf][nf][half * 2 + 0];
                float v1 = acc[mf][nf][half * 2 + 1];
                if (MODE == 0) {
                    *(float2*)(Dst + (size_t)(base + m0 + r) * Idim + col) =
                        make_float2(v0, v1);
                } else {
                    int tok = tokS[r];
                    float w = wgtS[r];
                    float* dst = Dst + (size_t)tok * Hdim + col;
                    atomicAdd(dst + 0, w * v0);
                    atomicAdd(dst + 1, w * v1);
                }
            }
        }
    }
}

// ---------------- h = silu(g) * u (fp16 for the down GEMM) ----------------
__global__ void silu_kernel() {
    size_t n = (size_t)TK * Idim;
    for (size_t i = (size_t)blockIdx.x * blockDim.x + threadIdx.x; i < n;
         i += (size_t)gridDim.x * blockDim.x) {
        float g = d_g[i], u = d_u[i];
        float h = g / (1.0f + expf(-g)) * u;
        d_h[i] = __float2half_rn(h);
    }
}

// ---------------- launch ----------------
extern "C" void kernel_launch(void* const* d_in, const int* in_sizes, int n_in,
                              void* d_out, int out_size) {
    const float* x  = (const float*)d_in[0];
    const float* nw = (const float*)d_in[1];
    const float* rw = (const float*)d_in[2];
    const float* wg = (const float*)d_in[3];
    const float* wu = (const float*)d_in[4];
    const float* wd = (const float*)d_in[5];
    float* out = (float*)d_out;

    static bool attr_done = false;
    if (!attr_done) {
        cudaFuncSetAttribute(mma_gemm<0>, cudaFuncAttributeMaxDynamicSharedMemorySize, SMEM_TOT);
        cudaFuncSetAttribute(mma_gemm<1>, cudaFuncAttributeMaxDynamicSharedMemorySize, SMEM_TOT);
        attr_done = true;
    }

    init_kernel<<<512, 256>>>(out);
    routing_kernel<<<Tdim, 256>>>(x, nw, rw);
    scan_kernel<<<1, 32>>>();
    assign_kernel<<<Tdim / 256, 256>>>();

    // gate+up in one launch: z = expert*2 + {0:gate, 1:up}
    dim3 g1(TK / 128, Idim / 128, Edim * 2);   // 32 x 32 x 16, most x exit early
    mma_gemm<0><<<g1, 256, SMEM_TOT>>>(wg, wu, nullptr);

    silu_kernel<<<2048, 256>>>();

    dim3 g2(TK / 128, Hdim / 128, Edim);       // 32 x 16 x 8
    mma_gemm<1><<<g2, 256, SMEM_TOT>>>(wd, nullptr, out);
}